// round 4
// baseline (speedup 1.0000x reference)
#include <cuda_runtime.h>
#include <cstdint>

#define N_NODES 50000
#define N_EDGES 800000
#define IN_DIM  256
#define HIDDEN  128
#define OUT_DIM 64
#define NEG_SLOPE 0.1f

// ---------------- scratch (static __device__, no allocation) ----------------
__device__ __align__(256) float g_buf0[N_NODES * HIDDEN];   // h ping
__device__ __align__(256) float g_buf1[N_NODES * HIDDEN];   // h pong / agg
__device__ float g_dinv[N_NODES];
__device__ int   g_cnt[N_NODES];             // in-degree histogram (edges only)
__device__ int   g_wp[N_NODES];              // write pointers for CSR fill
__device__ int   g_rowptr[N_NODES + 1];
__device__ int   g_col[N_EDGES];             // src per CSR slot
__device__ int   g_is64;                     // edge_index dtype flag

// sel: 0 -> g_buf0, 1 -> g_buf1, -1 -> passed pointer.
__device__ __forceinline__ const float* resolve_c(const float* p, int sel) {
    if (sel == 0) return g_buf0;
    if (sel == 1) return g_buf1;
    return p;
}
__device__ __forceinline__ float* resolve_m(float* p, int sel) {
    if (sel == 0) return g_buf0;
    if (sel == 1) return g_buf1;
    return p;
}

// ---------------- edge dtype detection ----------------
// If data is int32, the buffer holds 1.6M ints = 6.4MB = 800000 int64 slots,
// so sampling int64 slots < 800000 is in-bounds for BOTH dtypes.
// int32 data read as int64 packs two node ids -> value >= 2^32 unless the
// high word is 0 (prob ~1/50000 per sample). 2048 samples -> certainty.
__global__ void k_detect(const void* __restrict__ ei) {
    __shared__ int bad64;
    if (threadIdx.x == 0) bad64 = 0;
    __syncthreads();
    const long long* p64 = (const long long*)ei;
    int local = 0;
    for (int i = threadIdx.x; i < 2048; i += blockDim.x) {
        long long v = p64[(long long)i * 390];   // spread over first 800k slots
        if (v < 0 || v >= N_NODES) local++;
    }
    if (local) atomicAdd(&bad64, local);
    __syncthreads();
    if (threadIdx.x == 0) g_is64 = (bad64 == 0) ? 1 : 0;
}

__device__ __forceinline__ int edge_at(const void* ei, int which, int i) {
    if (g_is64) {
        long long v = ((const long long*)ei)[(size_t)which * N_EDGES + i];
        return (int)v;
    } else {
        return ((const int*)ei)[which * N_EDGES + i];
    }
}

// ---------------- graph preprocessing ----------------
__global__ void k_init_counts() {
    int i = blockIdx.x * blockDim.x + threadIdx.x;
    if (i < N_NODES) { g_cnt[i] = 0; g_wp[i] = 0; }
}

__global__ void k_count(const void* __restrict__ ei) {
    int i = blockIdx.x * blockDim.x + threadIdx.x;
    if (i < N_EDGES) {
        int d = edge_at(ei, 1, i);
        if ((unsigned)d < N_NODES) atomicAdd(&g_cnt[d], 1);
    }
}

__global__ void k_dinv() {
    int i = blockIdx.x * blockDim.x + threadIdx.x;
    if (i < N_NODES) g_dinv[i] = rsqrtf((float)(g_cnt[i] + 1)); // +1 self loop
}

// single-block exclusive scan over 50000 ints
__global__ void k_scan() {
    __shared__ int sh[1024];
    const int tid = threadIdx.x;
    const int CH = (N_NODES + 1023) / 1024;     // 49
    int start = tid * CH;
    int end   = start + CH; if (end > N_NODES) end = N_NODES;
    int s = 0;
    for (int i = start; i < end; i++) s += g_cnt[i];
    sh[tid] = s;
    __syncthreads();
    for (int d = 1; d < 1024; d <<= 1) {
        int t = (tid >= d) ? sh[tid - d] : 0;
        __syncthreads();
        sh[tid] += t;
        __syncthreads();
    }
    int off = sh[tid] - s;                       // exclusive
    for (int i = start; i < end; i++) {
        g_rowptr[i] = off;
        off += g_cnt[i];
    }
    if (start < N_NODES && end == N_NODES) g_rowptr[N_NODES] = off;
}

__global__ void k_fill(const void* __restrict__ ei) {
    int i = blockIdx.x * blockDim.x + threadIdx.x;
    if (i < N_EDGES) {
        int s = edge_at(ei, 0, i);
        int d = edge_at(ei, 1, i);
        if ((unsigned)d < N_NODES && (unsigned)s < N_NODES) {
            int pos = g_rowptr[d] + atomicAdd(&g_wp[d], 1);
            g_col[pos] = s;
        }
    }
}

// ---------------- aggregation: one warp per node, no float atomics -----------
// out[n] = dinv[n] * ( sum_{s in nbr(n)} dinv[s]*h[s]  +  dinv[n]*h[n] )
__global__ void k_agg(int in_sel, int out_sel) {
    const float* __restrict__ h = resolve_c(nullptr, in_sel);
    float* __restrict__ out = resolve_m(nullptr, out_sel);

    int warp = (blockIdx.x * blockDim.x + threadIdx.x) >> 5;
    int lane = threadIdx.x & 31;
    if (warp >= N_NODES) return;
    const int node = warp;
    const float dn = g_dinv[node];

    float4 self = *(const float4*)&h[(size_t)node * HIDDEN + lane * 4];
    float4 acc;
    acc.x = dn * self.x; acc.y = dn * self.y;
    acc.z = dn * self.z; acc.w = dn * self.w;

    const int beg = g_rowptr[node];
    const int end = g_rowptr[node + 1];
    for (int j = beg; j < end; j++) {
        int s = g_col[j];                 // broadcast load (same addr per warp)
        float ds = g_dinv[s];
        float4 v = *(const float4*)&h[(size_t)s * HIDDEN + lane * 4];
        acc.x = fmaf(ds, v.x, acc.x);
        acc.y = fmaf(ds, v.y, acc.y);
        acc.z = fmaf(ds, v.z, acc.z);
        acc.w = fmaf(ds, v.w, acc.w);
    }
    acc.x *= dn; acc.y *= dn; acc.z *= dn; acc.w *= dn;
    *(float4*)&out[(size_t)node * HIDDEN + lane * 4] = acc;
}

// ---------------- GEMM + bias (+ optional leaky relu) ------------------------
// C[M,N] = act(A[M,K] @ B[K,N] + bias[N])
template <int BM, int BN, int BK, int TM, int TN, bool ACT>
__global__ void gemm_bias(const float* __restrict__ A_ext,
                          const float* __restrict__ B,
                          const float* __restrict__ bias,
                          float* __restrict__ C_ext,
                          int a_sel, int c_sel,
                          int M, int K, int N) {
    const float* __restrict__ A = resolve_c(A_ext, a_sel);
    float* __restrict__ C = resolve_m(C_ext, c_sel);

    __shared__ float As[BK][BM];
    __shared__ float Bs[BK][BN];
    constexpr int NT = (BM / TM) * (BN / TN);
    const int tid = threadIdx.x;
    const int tx  = tid % (BN / TN);
    const int ty  = tid / (BN / TN);
    const int block_row = blockIdx.y * BM;
    const int block_col = blockIdx.x * BN;

    float acc[TM][TN];
#pragma unroll
    for (int i = 0; i < TM; i++)
#pragma unroll
        for (int j = 0; j < TN; j++) acc[i][j] = 0.0f;

    for (int k0 = 0; k0 < K; k0 += BK) {
#pragma unroll
        for (int t = tid; t < BM * BK / 4; t += NT) {
            int r  = t / (BK / 4);
            int c4 = t % (BK / 4);
            int grow = block_row + r;
            float4 v = make_float4(0.f, 0.f, 0.f, 0.f);
            if (grow < M)
                v = *(const float4*)&A[(size_t)grow * K + k0 + c4 * 4];
            As[c4 * 4 + 0][r] = v.x;
            As[c4 * 4 + 1][r] = v.y;
            As[c4 * 4 + 2][r] = v.z;
            As[c4 * 4 + 3][r] = v.w;
        }
#pragma unroll
        for (int t = tid; t < BK * BN / 4; t += NT) {
            int r  = t / (BN / 4);
            int c4 = t % (BN / 4);
            *(float4*)&Bs[r][c4 * 4] =
                *(const float4*)&B[(size_t)(k0 + r) * N + block_col + c4 * 4];
        }
        __syncthreads();

#pragma unroll
        for (int kk = 0; kk < BK; kk++) {
            float a[TM], b[TN];
#pragma unroll
            for (int i = 0; i < TM; i++) a[i] = As[kk][ty * TM + i];
#pragma unroll
            for (int j = 0; j < TN; j++) b[j] = Bs[kk][tx * TN + j];
#pragma unroll
            for (int i = 0; i < TM; i++)
#pragma unroll
                for (int j = 0; j < TN; j++)
                    acc[i][j] = fmaf(a[i], b[j], acc[i][j]);
        }
        __syncthreads();
    }

#pragma unroll
    for (int i = 0; i < TM; i++) {
        int grow = block_row + ty * TM + i;
        if (grow >= M) continue;
#pragma unroll
        for (int j = 0; j < TN; j += 4) {
            int gcol = block_col + tx * TN + j;
            float4 v;
            v.x = acc[i][j + 0] + bias[gcol + 0];
            v.y = acc[i][j + 1] + bias[gcol + 1];
            v.z = acc[i][j + 2] + bias[gcol + 2];
            v.w = acc[i][j + 3] + bias[gcol + 3];
            if (ACT) {
                v.x = v.x > 0.f ? v.x : NEG_SLOPE * v.x;
                v.y = v.y > 0.f ? v.y : NEG_SLOPE * v.y;
                v.z = v.z > 0.f ? v.z : NEG_SLOPE * v.z;
                v.w = v.w > 0.f ? v.w : NEG_SLOPE * v.w;
            }
            *(float4*)&C[(size_t)grow * N + gcol] = v;
        }
    }
}

// ---------------- launch ----------------
extern "C" void kernel_launch(void* const* d_in, const int* in_sizes, int n_in,
                              void* d_out, int out_size) {
    // Identify inputs by element count (robust to metadata ordering).
    int ix = -1, iei = -1, iencb = -1, iconvb = -1, idecW = -1, idecb = -1;
    for (int i = 0; i < n_in; i++) {
        switch (in_sizes[i]) {
            case 12800000: ix = i;     break;   // x [50000,256]
            case 1600000:  iei = i;    break;   // edge_index [2,800000]
            case 128:      iencb = i;  break;   // enc_b
            case 256:      iconvb = i; break;   // conv_b [2,128]
            case 8192:     idecW = i;  break;   // dec_W [128,64]
            case 64:       idecb = i;  break;   // dec_b
            default: break;                      // 32768: enc_W / conv_W
        }
    }
    // enc_W immediately precedes enc_b, conv_W immediately precedes conv_b
    // (true for both insertion order and alphabetical order).
    int iencW = -1, iconvW = -1;
    for (int i = 0; i < n_in; i++) {
        if (in_sizes[i] == 32768) {
            if (i == iencb - 1) iencW = i;
            else if (i == iconvb - 1) iconvW = i;
        }
    }
    if (iencW < 0 || iconvW < 0) {  // fallback: insertion order
        iencW = 2; iconvW = 4;
    }

    const float* x      = (const float*)d_in[ix];
    const void*  ei     = d_in[iei];
    const float* enc_W  = (const float*)d_in[iencW];
    const float* enc_b  = (const float*)d_in[iencb];
    const float* conv_W = (const float*)d_in[iconvW];
    const float* conv_b = (const float*)d_in[iconvb];
    const float* dec_W  = (const float*)d_in[idecW];
    const float* dec_b  = (const float*)d_in[idecb];
    float*       out    = (float*)d_out;

    // ---- preprocessing: dtype detect, CSR by dst, dinv ----
    k_detect<<<1, 256>>>(ei);
    k_init_counts<<<(N_NODES + 255) / 256, 256>>>();
    k_count<<<(N_EDGES + 255) / 256, 256>>>(ei);
    k_dinv<<<(N_NODES + 255) / 256, 256>>>();
    k_scan<<<1, 1024>>>();
    k_fill<<<(N_EDGES + 255) / 256, 256>>>(ei);

    // ---- encoder: h0 = lrelu(x @ enc_W + enc_b) ----
    {
        dim3 grid(HIDDEN / 128, (N_NODES + 127) / 128);
        gemm_bias<128, 128, 16, 8, 8, true><<<grid, 256>>>(
            x, enc_W, enc_b, nullptr, -1, 0, N_NODES, IN_DIM, HIDDEN);
    }

    // ---- 2 GCN layers ----
    dim3 ggrid(HIDDEN / 128, (N_NODES + 127) / 128);
    int agg_blocks = (N_NODES * 32 + 255) / 256;
    for (int l = 0; l < 2; l++) {
        k_agg<<<agg_blocks, 256>>>(0, 1);
        gemm_bias<128, 128, 16, 8, 8, true><<<ggrid, 256>>>(
            nullptr, conv_W + (size_t)l * HIDDEN * HIDDEN,
            conv_b + (size_t)l * HIDDEN, nullptr, 1, 0,
            N_NODES, HIDDEN, HIDDEN);
    }

    // ---- decoder: out = h @ dec_W + dec_b ----
    {
        dim3 grid(OUT_DIM / 64, (N_NODES + 127) / 128);
        gemm_bias<128, 64, 16, 8, 4, false><<<grid, 256>>>(
            nullptr, dec_W, dec_b, out, 0, -1, N_NODES, HIDDEN, OUT_DIM);
    }
}

// round 7
// speedup vs baseline: 1.4089x; 1.4089x over previous
#include <cuda_runtime.h>
#include <cuda_bf16.h>
#include <cstdint>

#define N_NODES 50000
#define N_EDGES 800000
#define IN_DIM  256
#define HIDDEN  128
#define OUT_DIM 64
#define NEG_SLOPE 0.1f

// ============================ PTX helpers (sm_80+ baseline) ==================
__device__ __forceinline__ uint32_t smem_u32(const void* p) {
    uint32_t a;
    asm("{ .reg .u64 t; cvta.to.shared.u64 t, %1; cvt.u32.u64 %0, t; }"
        : "=r"(a) : "l"(p));
    return a;
}
#define LDMX4(R, addr) \
    asm volatile("ldmatrix.sync.aligned.m8n8.x4.shared.b16 {%0,%1,%2,%3}, [%4];" \
        : "=r"((R)[0]), "=r"((R)[1]), "=r"((R)[2]), "=r"((R)[3]) : "r"(addr))
#define MMA16816(d, a, b) \
    asm volatile("mma.sync.aligned.m16n8k16.row.col.f32.bf16.bf16.f32 " \
        "{%0,%1,%2,%3},{%4,%5,%6,%7},{%8,%9},{%0,%1,%2,%3};" \
        : "+f"((d)[0]), "+f"((d)[1]), "+f"((d)[2]), "+f"((d)[3]) \
        : "r"((a)[0]), "r"((a)[1]), "r"((a)[2]), "r"((a)[3]), \
          "r"((b)[0]), "r"((b)[1]))

__device__ __forceinline__ uint32_t pack_bf2(__nv_bfloat16 a, __nv_bfloat16 b) {
    __nv_bfloat162 p; p.x = a; p.y = b;
    return *(uint32_t*)&p;
}

// ---------------- scratch (static __device__, no allocation) ----------------
__device__ __align__(256) float g_buf0[N_NODES * HIDDEN];
__device__ __align__(256) float g_buf1[N_NODES * HIDDEN];
__device__ float g_dinv[N_NODES];
__device__ int   g_cnt[N_NODES];
__device__ int   g_wp[N_NODES];
__device__ int   g_rowptr[N_NODES + 1];
__device__ int   g_col[N_EDGES];
__device__ int   g_is64;
// pre-transposed + bf16-split weights: Wt[n][k] hi/lo
__device__ __align__(16) __nv_bfloat16 g_wthi_enc[HIDDEN * IN_DIM];
__device__ __align__(16) __nv_bfloat16 g_wtlo_enc[HIDDEN * IN_DIM];
__device__ __align__(16) __nv_bfloat16 g_wthi_conv[2 * HIDDEN * HIDDEN];
__device__ __align__(16) __nv_bfloat16 g_wtlo_conv[2 * HIDDEN * HIDDEN];
__device__ __align__(16) __nv_bfloat16 g_wthi_dec[OUT_DIM * HIDDEN];
__device__ __align__(16) __nv_bfloat16 g_wtlo_dec[OUT_DIM * HIDDEN];

__device__ __forceinline__ const float* resolve_c(const float* p, int sel) {
    if (sel == 0) return g_buf0;
    if (sel == 1) return g_buf1;
    return p;
}
__device__ __forceinline__ float* resolve_m(float* p, int sel) {
    if (sel == 0) return g_buf0;
    if (sel == 1) return g_buf1;
    return p;
}

// ---------------- edge dtype detection (int64 vs int32) ----------------
__global__ void k_detect(const void* __restrict__ ei) {
    __shared__ int bad64;
    if (threadIdx.x == 0) bad64 = 0;
    __syncthreads();
    const long long* p64 = (const long long*)ei;
    int local = 0;
    for (int i = threadIdx.x; i < 2048; i += blockDim.x) {
        long long v = p64[(long long)i * 390];
        if (v < 0 || v >= N_NODES) local++;
    }
    if (local) atomicAdd(&bad64, local);
    __syncthreads();
    if (threadIdx.x == 0) g_is64 = (bad64 == 0) ? 1 : 0;
}
__device__ __forceinline__ int edge_at(const void* ei, int which, int i) {
    if (g_is64) return (int)((const long long*)ei)[(size_t)which * N_EDGES + i];
    return ((const int*)ei)[which * N_EDGES + i];
}

// ---------------- graph preprocessing ----------------
__global__ void k_init_counts() {
    int i = blockIdx.x * blockDim.x + threadIdx.x;
    if (i < N_NODES) { g_cnt[i] = 0; g_wp[i] = 0; }
}
__global__ void k_count(const void* __restrict__ ei) {
    int i = blockIdx.x * blockDim.x + threadIdx.x;
    if (i < N_EDGES) {
        int d = edge_at(ei, 1, i);
        if ((unsigned)d < N_NODES) atomicAdd(&g_cnt[d], 1);
    }
}
__global__ void k_dinv() {
    int i = blockIdx.x * blockDim.x + threadIdx.x;
    if (i < N_NODES) g_dinv[i] = rsqrtf((float)(g_cnt[i] + 1));
}
__global__ void k_scan() {
    __shared__ int sh[1024];
    const int tid = threadIdx.x;
    const int CH = (N_NODES + 1023) / 1024;
    int start = tid * CH;
    int end   = start + CH; if (end > N_NODES) end = N_NODES;
    int s = 0;
    for (int i = start; i < end; i++) s += g_cnt[i];
    sh[tid] = s;
    __syncthreads();
    for (int d = 1; d < 1024; d <<= 1) {
        int t = (tid >= d) ? sh[tid - d] : 0;
        __syncthreads();
        sh[tid] += t;
        __syncthreads();
    }
    int off = sh[tid] - s;
    for (int i = start; i < end; i++) { g_rowptr[i] = off; off += g_cnt[i]; }
    if (start < N_NODES && end == N_NODES) g_rowptr[N_NODES] = off;
}
__global__ void k_fill(const void* __restrict__ ei) {
    int i = blockIdx.x * blockDim.x + threadIdx.x;
    if (i < N_EDGES) {
        int s = edge_at(ei, 0, i);
        int d = edge_at(ei, 1, i);
        if ((unsigned)d < N_NODES && (unsigned)s < N_NODES) {
            int pos = g_rowptr[d] + atomicAdd(&g_wp[d], 1);
            g_col[pos] = s;
        }
    }
}

// ---------------- weight prep: transpose + bf16 hi/lo split ----------------
__global__ void k_prep_w(const float* __restrict__ enc_W,
                         const float* __restrict__ conv_W,
                         const float* __restrict__ dec_W) {
    int idx = blockIdx.x * blockDim.x + threadIdx.x;
    const int E0 = HIDDEN * IN_DIM;
    const int C0 = E0 + 2 * HIDDEN * HIDDEN;
    const int T  = C0 + OUT_DIM * HIDDEN;
    if (idx >= T) return;
    const float* W; __nv_bfloat16 *hi, *lo; int K, N, li;
    if (idx < E0) { W = enc_W; hi = g_wthi_enc; lo = g_wtlo_enc; K = IN_DIM; N = HIDDEN; li = idx; }
    else if (idx < C0) {
        int j = idx - E0; int which = j / (HIDDEN * HIDDEN); li = j % (HIDDEN * HIDDEN);
        W = conv_W + (size_t)which * HIDDEN * HIDDEN;
        hi = g_wthi_conv + (size_t)which * HIDDEN * HIDDEN;
        lo = g_wtlo_conv + (size_t)which * HIDDEN * HIDDEN;
        K = HIDDEN; N = HIDDEN;
    } else { li = idx - C0; W = dec_W; hi = g_wthi_dec; lo = g_wtlo_dec; K = HIDDEN; N = OUT_DIM; }
    int k = li / N, n = li % N;
    float v = W[(size_t)k * N + n];
    __nv_bfloat16 h = __float2bfloat16(v);
    float r = v - __bfloat162float(h);
    hi[(size_t)n * K + k] = h;
    lo[(size_t)n * K + k] = __float2bfloat16(r);
}

// ---------------- aggregation: one warp per node ----------------
__global__ void k_agg(int in_sel, int out_sel) {
    const float* __restrict__ h = resolve_c(nullptr, in_sel);
    float* __restrict__ out = resolve_m(nullptr, out_sel);
    int warp = (blockIdx.x * blockDim.x + threadIdx.x) >> 5;
    int lane = threadIdx.x & 31;
    if (warp >= N_NODES) return;
    const int node = warp;
    const float dn = g_dinv[node];
    float4 self = *(const float4*)&h[(size_t)node * HIDDEN + lane * 4];
    float4 acc;
    acc.x = dn * self.x; acc.y = dn * self.y;
    acc.z = dn * self.z; acc.w = dn * self.w;
    const int beg = g_rowptr[node];
    const int end = g_rowptr[node + 1];
    for (int j = beg; j < end; j++) {
        int s = g_col[j];
        float ds = g_dinv[s];
        float4 v = *(const float4*)&h[(size_t)s * HIDDEN + lane * 4];
        acc.x = fmaf(ds, v.x, acc.x);
        acc.y = fmaf(ds, v.y, acc.y);
        acc.z = fmaf(ds, v.z, acc.z);
        acc.w = fmaf(ds, v.w, acc.w);
    }
    acc.x *= dn; acc.y *= dn; acc.z *= dn; acc.w *= dn;
    *(float4*)&out[(size_t)node * HIDDEN + lane * 4] = acc;
}

// ============ bf16x3 GEMM via mma.sync.m16n8k16 (sm_80+ baseline) ============
// C[M,N] = act(A[M,KTOT] @ W + b).  A fp32 split per tile; Wt pre-split bf16.
// CTA: 256 thr = 8 warps (4m x 2n).  BM=128, BN=N, BK=32.
// Warp tile: 32 rows x N/2 cols.  WSEL: 0=enc,1=conv0,2=conv1,3=dec.
template <int KTOT, int N, int WSEL, bool ACT>
__global__ void __launch_bounds__(256, 1)
gemm_mma(const float* __restrict__ A_ext, int a_sel,
         const float* __restrict__ bias,
         float* __restrict__ C_ext, int c_sel, int M) {
    constexpr int NTPW = N / 16;        // n-tiles (8 cols) per warp
    const float* __restrict__ A = resolve_c(A_ext, a_sel);
    float* __restrict__ C = resolve_m(C_ext, c_sel);
    const __nv_bfloat16* __restrict__ WtHi;
    const __nv_bfloat16* __restrict__ WtLo;
    if (WSEL == 0)      { WtHi = g_wthi_enc;  WtLo = g_wtlo_enc; }
    else if (WSEL == 1) { WtHi = g_wthi_conv; WtLo = g_wtlo_conv; }
    else if (WSEL == 2) { WtHi = g_wthi_conv + HIDDEN * HIDDEN;
                          WtLo = g_wtlo_conv + HIDDEN * HIDDEN; }
    else                { WtHi = g_wthi_dec;  WtLo = g_wtlo_dec; }

    // pad rows to 40 bf16 (80B): 80 = 5*16, gcd(5,8)=1 -> conflict-free ldmatrix
    __shared__ __align__(16) __nv_bfloat16 sAhi[128][40];
    __shared__ __align__(16) __nv_bfloat16 sAlo[128][40];
    __shared__ __align__(16) __nv_bfloat16 sBhi[N][40];
    __shared__ __align__(16) __nv_bfloat16 sBlo[N][40];

    const int tid  = threadIdx.x;
    const int lane = tid & 31;
    const int wid  = tid >> 5;
    const int wm   = wid & 3;            // warp m position (0..3)
    const int wn   = wid >> 2;           // warp n position (0..1)
    const int block_row = blockIdx.x * 128;

    float acc[2][NTPW][4];
#pragma unroll
    for (int mt = 0; mt < 2; mt++)
#pragma unroll
        for (int nt = 0; nt < NTPW; nt++)
#pragma unroll
            for (int j = 0; j < 4; j++) acc[mt][nt][j] = 0.0f;

    for (int k0 = 0; k0 < KTOT; k0 += 32) {
        // ---- stage A chunk: 128 rows x 32 fp32 -> hi/lo bf16 smem ----
        {
            const int row  = tid >> 1;
            const int half = tid & 1;
            const int gr   = block_row + row;
            const float* src = A + (size_t)gr * KTOT + k0 + half * 16;
            const bool ok = gr < M;
#pragma unroll
            for (int j = 0; j < 4; j++) {
                float4 v = ok ? *(const float4*)(src + j * 4)
                              : make_float4(0.f, 0.f, 0.f, 0.f);
                __nv_bfloat16 hx = __float2bfloat16(v.x);
                __nv_bfloat16 hy = __float2bfloat16(v.y);
                __nv_bfloat16 hz = __float2bfloat16(v.z);
                __nv_bfloat16 hw = __float2bfloat16(v.w);
                __nv_bfloat16 lx = __float2bfloat16(v.x - __bfloat162float(hx));
                __nv_bfloat16 ly = __float2bfloat16(v.y - __bfloat162float(hy));
                __nv_bfloat16 lz = __float2bfloat16(v.z - __bfloat162float(hz));
                __nv_bfloat16 lw = __float2bfloat16(v.w - __bfloat162float(hw));
                int col = half * 16 + j * 4;
                *(uint2*)&sAhi[row][col] = make_uint2(pack_bf2(hx, hy), pack_bf2(hz, hw));
                *(uint2*)&sAlo[row][col] = make_uint2(pack_bf2(lx, ly), pack_bf2(lz, lw));
            }
        }
        // ---- stage B chunk: N rows x 32 bf16 (hi and lo) ----
#pragma unroll
        for (int i = tid; i < N * 4; i += 256) {
            int row = i >> 2, q = i & 3;
            *(uint4*)&sBhi[row][q * 8] =
                *(const uint4*)(WtHi + (size_t)row * KTOT + k0 + q * 8);
            *(uint4*)&sBlo[row][q * 8] =
                *(const uint4*)(WtLo + (size_t)row * KTOT + k0 + q * 8);
        }
        __syncthreads();

#pragma unroll
        for (int ks = 0; ks < 2; ks++) {
            const int kb = ks * 16;
            // A fragments (2 m-tiles, hi+lo)
            uint32_t ahi[2][4], alo[2][4];
#pragma unroll
            for (int mt = 0; mt < 2; mt++) {
                int r = wm * 32 + mt * 16 + (lane & 7) + ((lane >> 3) & 1) * 8;
                int c = kb + (lane >> 4) * 8;
                LDMX4(ahi[mt], smem_u32(&sAhi[r][c]));
                LDMX4(alo[mt], smem_u32(&sAlo[r][c]));
            }
            // B fragments (NTPW n-tiles, hi+lo); x4 loads 2 n-tiles
            uint32_t bhi[NTPW][2], blo[NTPW][2];
#pragma unroll
            for (int p = 0; p < NTPW / 2; p++) {
                int n0 = wn * (N / 2) + p * 16;
                int r = n0 + (lane >> 4) * 8 + (lane & 7);
                int c = kb + ((lane >> 3) & 1) * 8;
                uint32_t r4[4];
                LDMX4(r4, smem_u32(&sBhi[r][c]));
                bhi[2 * p][0] = r4[0]; bhi[2 * p][1] = r4[1];
                bhi[2 * p + 1][0] = r4[2]; bhi[2 * p + 1][1] = r4[3];
                LDMX4(r4, smem_u32(&sBlo[r][c]));
                blo[2 * p][0] = r4[0]; blo[2 * p][1] = r4[1];
                blo[2 * p + 1][0] = r4[2]; blo[2 * p + 1][1] = r4[3];
            }
            // MMAs: hh + hl + lh
#pragma unroll
            for (int mt = 0; mt < 2; mt++)
#pragma unroll
                for (int nt = 0; nt < NTPW; nt++) {
                    MMA16816(acc[mt][nt], ahi[mt], bhi[nt]);
                    MMA16816(acc[mt][nt], ahi[mt], blo[nt]);
                    MMA16816(acc[mt][nt], alo[mt], bhi[nt]);
                }
        }
        __syncthreads();
    }

    // ---- epilogue: bias + (leaky relu) + store ----
#pragma unroll
    for (int mt = 0; mt < 2; mt++) {
#pragma unroll
        for (int nt = 0; nt < NTPW; nt++) {
            int col = wn * (N / 2) + nt * 8 + (lane & 3) * 2;
            float bx = bias[col], by = bias[col + 1];
            int row0 = block_row + wm * 32 + mt * 16 + (lane >> 2);
            if (row0 < M) {
                float vx = acc[mt][nt][0] + bx;
                float vy = acc[mt][nt][1] + by;
                if (ACT) {
                    vx = vx > 0.f ? vx : NEG_SLOPE * vx;
                    vy = vy > 0.f ? vy : NEG_SLOPE * vy;
                }
                *(float2*)&C[(size_t)row0 * N + col] = make_float2(vx, vy);
            }
            int row1 = row0 + 8;
            if (row1 < M) {
                float vx = acc[mt][nt][2] + bx;
                float vy = acc[mt][nt][3] + by;
                if (ACT) {
                    vx = vx > 0.f ? vx : NEG_SLOPE * vx;
                    vy = vy > 0.f ? vy : NEG_SLOPE * vy;
                }
                *(float2*)&C[(size_t)row1 * N + col] = make_float2(vx, vy);
            }
        }
    }
}

// ---------------- launch ----------------
extern "C" void kernel_launch(void* const* d_in, const int* in_sizes, int n_in,
                              void* d_out, int out_size) {
    int ix = -1, iei = -1, iencb = -1, iconvb = -1, idecW = -1, idecb = -1;
    for (int i = 0; i < n_in; i++) {
        switch (in_sizes[i]) {
            case 12800000: ix = i;     break;
            case 1600000:  iei = i;    break;
            case 128:      iencb = i;  break;
            case 256:      iconvb = i; break;
            case 8192:     idecW = i;  break;
            case 64:       idecb = i;  break;
            default: break;
        }
    }
    int iencW = -1, iconvW = -1;
    for (int i = 0; i < n_in; i++) {
        if (in_sizes[i] == 32768) {
            if (i == iencb - 1) iencW = i;
            else if (i == iconvb - 1) iconvW = i;
        }
    }
    if (iencW < 0 || iconvW < 0) { iencW = 2; iconvW = 4; }

    const float* x      = (const float*)d_in[ix];
    const void*  ei     = d_in[iei];
    const float* enc_W  = (const float*)d_in[iencW];
    const float* enc_b  = (const float*)d_in[iencb];
    const float* conv_W = (const float*)d_in[iconvW];
    const float* conv_b = (const float*)d_in[iconvb];
    const float* dec_W  = (const float*)d_in[idecW];
    const float* dec_b  = (const float*)d_in[idecb];
    float*       out    = (float*)d_out;

    // ---- preprocessing ----
    k_detect<<<1, 256>>>(ei);
    k_init_counts<<<(N_NODES + 255) / 256, 256>>>();
    k_count<<<(N_EDGES + 255) / 256, 256>>>(ei);
    k_dinv<<<(N_NODES + 255) / 256, 256>>>();
    k_scan<<<1, 1024>>>();
    k_fill<<<(N_EDGES + 255) / 256, 256>>>(ei);
    k_prep_w<<<(73728 + 255) / 256, 256>>>(enc_W, conv_W, dec_W);

    const int NTILES = (N_NODES + 127) / 128;   // 391

    // ---- encoder: h0 = lrelu(x @ enc_W + enc_b) ----
    gemm_mma<IN_DIM, HIDDEN, 0, true><<<NTILES, 256>>>(
        x, -1, enc_b, nullptr, 0, N_NODES);

    // ---- GCN layers ----
    int agg_blocks = (N_NODES * 32 + 255) / 256;
    k_agg<<<agg_blocks, 256>>>(0, 1);
    gemm_mma<HIDDEN, HIDDEN, 1, true><<<NTILES, 256>>>(
        nullptr, 1, conv_b, nullptr, 0, N_NODES);
    k_agg<<<agg_blocks, 256>>>(0, 1);
    gemm_mma<HIDDEN, HIDDEN, 2, true><<<NTILES, 256>>>(
        nullptr, 1, conv_b + HIDDEN, nullptr, 0, N_NODES);

    // ---- decoder: out = h @ dec_W + dec_b ----
    gemm_mma<HIDDEN, OUT_DIM, 3, false><<<NTILES, 256>>>(
        nullptr, 0, dec_b, out, -1, N_NODES);
}